// round 7
// baseline (speedup 1.0000x reference)
#include <cuda_runtime.h>
#include <cstdint>

// Problem constants
#define B    8
#define D    256
#define TC   2048
#define TE   2048
#define TGT  256
#define K3   1536            // 512 channels * 3 taps (im2col K)
#define INV_SCALE 0.0625f    // 1/16

#define SST 20               // smem row stride in floats (16 data + 4 pad)

// ---------------------------------------------------------------------------
// Scratch (allocation-free rule: __device__ globals)
// ---------------------------------------------------------------------------
static __device__ float g_sim[(size_t)B * TC * TE];   // 134 MB logits/attn
static __device__ float g_wT[(size_t)B * D * TC];     // 16.8 MB weighted^T

// ---------------------------------------------------------------------------
// Helpers
// ---------------------------------------------------------------------------
__device__ __forceinline__ uint32_t to_tf32(float x) {
    uint32_t r;
    asm("cvt.rna.tf32.f32 %0, %1;" : "=r"(r) : "f"(x));
    return r;
}

__device__ __forceinline__ void mma8(float c[4], const uint32_t a[4],
                                     uint32_t b0, uint32_t b1) {
    asm volatile(
        "mma.sync.aligned.m16n8k8.row.col.f32.tf32.tf32.f32 "
        "{%0,%1,%2,%3}, {%4,%5,%6,%7}, {%8,%9}, {%0,%1,%2,%3};"
        : "+f"(c[0]), "+f"(c[1]), "+f"(c[2]), "+f"(c[3])
        : "r"(a[0]), "r"(a[1]), "r"(a[2]), "r"(a[3]), "r"(b0), "r"(b1));
}

// ---------------------------------------------------------------------------
// Staging: tiles are [128 rows][16 k] fp32 (tf32-rounded), row stride SST.
// ---------------------------------------------------------------------------

// Operand K-major in global ([row][k], k contiguous): float4 path.
__device__ __forceinline__ void ldg_km(const float* g, int stride, int k0,
                                       int tid, float4 r[2]) {
#pragma unroll
    for (int it = 0; it < 2; it++) {
        const int idx = it * 256 + tid;          // 0..511
        const int k4 = idx & 3, row = idx >> 2;  // k4*4, row 0..127
        r[it] = *(const float4*)(g + (size_t)row * stride + k0 + k4 * 4);
    }
}
__device__ __forceinline__ void sts_km(uint32_t* S, int tid, const float4 r[2]) {
#pragma unroll
    for (int it = 0; it < 2; it++) {
        const int idx = it * 256 + tid;
        const int k4 = idx & 3, row = idx >> 2;
        uint4 v;
        v.x = to_tf32(r[it].x); v.y = to_tf32(r[it].y);
        v.z = to_tf32(r[it].z); v.w = to_tf32(r[it].w);
        *(uint4*)(S + row * SST + k4 * 4) = v;
    }
}

// Operand MN-major in global ([k][row], row contiguous): transpose staging.
__device__ __forceinline__ void ldg_tr(const float* g, int stride, int k0,
                                       int tid, float r[8]) {
#pragma unroll
    for (int it = 0; it < 8; it++) {
        const int idx = it * 256 + tid;          // 0..2047
        const int k = idx >> 7, m = idx & 127;
        r[it] = g[(size_t)(k0 + k) * stride + m];
    }
}
__device__ __forceinline__ void sts_tr(uint32_t* S, int tid, const float r[8]) {
#pragma unroll
    for (int it = 0; it < 8; it++) {
        const int idx = it * 256 + tid;
        const int k = idx >> 7, m = idx & 127;
        S[m * SST + k] = to_tf32(r[it]);
    }
}

// Conv B operand: on-the-fly im2col from X = concat(content, wT) rows.
// Bs[t][kk] with k = k0+kk, c = k/3, tap = k%3, tt = t0+t+tap-1.
__device__ __forceinline__ void ldg_conv(const float* cbase, const float* wbase,
                                         int t0, int k0, int tid, float r[8]) {
#pragma unroll
    for (int it = 0; it < 8; it++) {
        const int idx = it * 256 + tid;          // 0..2047
        const int kk = idx >> 7, t = idx & 127;  // lanes: consecutive t
        const int k = k0 + kk;
        const int c = k / 3, tap = k - 3 * c;
        const int tt = t0 + t + tap - 1;
        float v = 0.f;
        if (tt >= 0 && tt < TC)
            v = (c < D) ? cbase[(size_t)c * TC + tt]
                        : wbase[(size_t)(c - D) * TC + tt];
        r[it] = v;
    }
}
__device__ __forceinline__ void sts_conv(uint32_t* S, int tid, const float r[8]) {
#pragma unroll
    for (int it = 0; it < 8; it++) {
        const int idx = it * 256 + tid;
        const int kk = idx >> 7, t = idx & 127;
        S[t * SST + kk] = to_tf32(r[it]);
    }
}

// ---------------------------------------------------------------------------
// Core warp-tile compute: one K=16 smem tile -> 32 HMMAs per warp.
// Warp tile 64(m) x 32(n); acc[mt][nt][4]. LDS pattern is bank-conflict-free.
// ---------------------------------------------------------------------------
__device__ __forceinline__ void compute_tile(const uint32_t* As, const uint32_t* Bs,
                                             int arow0, int bcol0, int gr, int tg,
                                             float acc[4][4][4]) {
#pragma unroll
    for (int ks = 0; ks < 16; ks += 8) {
        uint32_t a[4][4];
#pragma unroll
        for (int mt = 0; mt < 4; mt++) {
            const uint32_t* pa = As + (arow0 + mt * 16 + gr) * SST + ks + tg;
            a[mt][0] = pa[0];
            a[mt][2] = pa[4];
            a[mt][1] = pa[8 * SST];
            a[mt][3] = pa[8 * SST + 4];
        }
#pragma unroll
        for (int nt = 0; nt < 4; nt++) {
            const uint32_t* pb = Bs + (bcol0 + nt * 8 + gr) * SST + ks + tg;
            const uint32_t b0 = pb[0], b1 = pb[4];
#pragma unroll
            for (int mt = 0; mt < 4; mt++)
                mma8(acc[mt][nt], a[mt], b0, b1);
        }
    }
}

// ---------------------------------------------------------------------------
// GEMM1: sim[b][t][s] = (1/16) * sum_d C[b][d][t]*E[b][d][s]
// Both operands MN-major -> transpose staging. K=D=256 (16 tiles).
// 3-stage pipeline: 2 smem buffers + 2 register prefetch sets, 1 bar/tile.
// ---------------------------------------------------------------------------
__global__ __launch_bounds__(256, 2)
void gemm_qk(const float* __restrict__ content, const float* __restrict__ emotion)
{
    __shared__ uint32_t As[2][128 * SST];
    __shared__ uint32_t Bs[2][128 * SST];

    const int b = blockIdx.z, t0 = blockIdx.x * 128, s0 = blockIdx.y * 128;
    const float* Ag = content + (size_t)b * D * TC + t0;
    const float* Bg = emotion + (size_t)b * D * TE + s0;

    const int tid = threadIdx.x, wid = tid >> 5, lane = tid & 31;
    const int wm = wid >> 2, wn = wid & 3;
    const int gr = lane >> 2, tg = lane & 3;
    const int arow0 = wm * 64, bcol0 = wn * 32;

    float acc[4][4][4] = {};
    float ra[2][8], rb[2][8];

    const int NT = D / 16;  // 16
    ldg_tr(Ag, TC, 0, tid, ra[0]);  ldg_tr(Bg, TE, 0, tid, rb[0]);
    ldg_tr(Ag, TC, 16, tid, ra[1]); ldg_tr(Bg, TE, 16, tid, rb[1]);
    sts_tr(As[0], tid, ra[0]);      sts_tr(Bs[0], tid, rb[0]);
    __syncthreads();

    for (int kt = 0; kt < NT; kt++) {
        const int cur = kt & 1, nxt = cur ^ 1;
        if (kt + 2 < NT) {
            ldg_tr(Ag, TC, (kt + 2) * 16, tid, ra[cur]);
            ldg_tr(Bg, TE, (kt + 2) * 16, tid, rb[cur]);
        }
        compute_tile(As[cur], Bs[cur], arow0, bcol0, gr, tg, acc);
        if (kt + 1 < NT) {
            sts_tr(As[nxt], tid, ra[nxt]);
            sts_tr(Bs[nxt], tid, rb[nxt]);
            __syncthreads();
        }
    }

    float* dst = g_sim + ((size_t)b * TC) * TE;
#pragma unroll
    for (int mt = 0; mt < 4; mt++) {
        const int r0 = t0 + arow0 + mt * 16 + gr;
#pragma unroll
        for (int nt = 0; nt < 4; nt++) {
            const int c = s0 + bcol0 + nt * 8 + tg * 2;
            float2 v0 = { acc[mt][nt][0] * INV_SCALE, acc[mt][nt][1] * INV_SCALE };
            float2 v1 = { acc[mt][nt][2] * INV_SCALE, acc[mt][nt][3] * INV_SCALE };
            *(float2*)(dst + (size_t)r0 * TE + c) = v0;
            *(float2*)(dst + (size_t)(r0 + 8) * TE + c) = v1;
        }
    }
}

// ---------------------------------------------------------------------------
// Row softmax over TE=2048, in place.
// ---------------------------------------------------------------------------
__global__ __launch_bounds__(256) void softmax_kernel()
{
    const size_t row = blockIdx.x;
    float* p = g_sim + row * TE;
    const int tid = threadIdx.x;

    float v[8];
    float mx = -1e30f;
#pragma unroll
    for (int j = 0; j < 8; j++) {
        v[j] = p[tid + j * 256];
        mx = fmaxf(mx, v[j]);
    }
    __shared__ float red[256];
    red[tid] = mx;
    __syncthreads();
    for (int s = 128; s > 0; s >>= 1) {
        if (tid < s) red[tid] = fmaxf(red[tid], red[tid + s]);
        __syncthreads();
    }
    mx = red[0];
    __syncthreads();

    float sum = 0.f;
#pragma unroll
    for (int j = 0; j < 8; j++) { v[j] = __expf(v[j] - mx); sum += v[j]; }
    red[tid] = sum;
    __syncthreads();
    for (int s = 128; s > 0; s >>= 1) {
        if (tid < s) red[tid] += red[tid + s];
        __syncthreads();
    }
    const float inv = 1.0f / red[0];
#pragma unroll
    for (int j = 0; j < 8; j++) p[tid + j * 256] = v[j] * inv;
}

// ---------------------------------------------------------------------------
// GEMM2: wT[b][d][t] = sum_s E[b][d][s]*attn[b][t][s]
// Both K-major. K=TE=2048 (128 tiles). 3-stage pipeline.
// ---------------------------------------------------------------------------
__global__ __launch_bounds__(256, 2)
void gemm_av(const float* __restrict__ emotion)
{
    __shared__ uint32_t As[2][128 * SST];
    __shared__ uint32_t Bs[2][128 * SST];

    const int b = blockIdx.z, n0 = blockIdx.x * 128, m0 = blockIdx.y * 128;
    const float* Ag = emotion + (size_t)b * D * TE + (size_t)m0 * TE;
    const float* Bg = g_sim + (size_t)b * TC * TE + (size_t)n0 * TE;

    const int tid = threadIdx.x, wid = tid >> 5, lane = tid & 31;
    const int wm = wid >> 2, wn = wid & 3;
    const int gr = lane >> 2, tg = lane & 3;
    const int arow0 = wm * 64, bcol0 = wn * 32;

    float acc[4][4][4] = {};
    float4 ra[2][2], rb[2][2];

    const int NT = TE / 16;  // 128
    ldg_km(Ag, TE, 0, tid, ra[0]);  ldg_km(Bg, TE, 0, tid, rb[0]);
    ldg_km(Ag, TE, 16, tid, ra[1]); ldg_km(Bg, TE, 16, tid, rb[1]);
    sts_km(As[0], tid, ra[0]);      sts_km(Bs[0], tid, rb[0]);
    __syncthreads();

    for (int kt = 0; kt < NT; kt++) {
        const int cur = kt & 1, nxt = cur ^ 1;
        if (kt + 2 < NT) {
            ldg_km(Ag, TE, (kt + 2) * 16, tid, ra[cur]);
            ldg_km(Bg, TE, (kt + 2) * 16, tid, rb[cur]);
        }
        compute_tile(As[cur], Bs[cur], arow0, bcol0, gr, tg, acc);
        if (kt + 1 < NT) {
            sts_km(As[nxt], tid, ra[nxt]);
            sts_km(Bs[nxt], tid, rb[nxt]);
            __syncthreads();
        }
    }

    float* dst = g_wT + ((size_t)b * D) * TC;
#pragma unroll
    for (int mt = 0; mt < 4; mt++) {
        const int r0 = m0 + arow0 + mt * 16 + gr;   // d
#pragma unroll
        for (int nt = 0; nt < 4; nt++) {
            const int c = n0 + bcol0 + nt * 8 + tg * 2;  // t
            float2 v0 = { acc[mt][nt][0], acc[mt][nt][1] };
            float2 v1 = { acc[mt][nt][2], acc[mt][nt][3] };
            *(float2*)(dst + (size_t)r0 * TC + c) = v0;
            *(float2*)(dst + (size_t)(r0 + 8) * TC + c) = v1;
        }
    }
}

// ---------------------------------------------------------------------------
// Conv as GEMM with fused im2col:
// out[b][o][t] = bias[o] + sum_k W[o][k] * X[c(k)][t + tap(k) - 1]
// A = conv_w (K-major), B staged on the fly from content/g_wT. K=1536.
// ---------------------------------------------------------------------------
__global__ __launch_bounds__(256, 2)
void conv_mm(const float* __restrict__ content, const float* __restrict__ w,
             const float* __restrict__ bias, float* __restrict__ out)
{
    __shared__ uint32_t As[2][128 * SST];
    __shared__ uint32_t Bs[2][128 * SST];

    const int b = blockIdx.z, n0 = blockIdx.x * 128, m0 = blockIdx.y * 128;
    const float* Ag = w + (size_t)m0 * K3;
    const float* cbase = content + (size_t)b * D * TC;
    const float* wbase = g_wT + (size_t)b * D * TC;

    const int tid = threadIdx.x, wid = tid >> 5, lane = tid & 31;
    const int wm = wid >> 2, wn = wid & 3;
    const int gr = lane >> 2, tg = lane & 3;
    const int arow0 = wm * 64, bcol0 = wn * 32;

    float acc[4][4][4] = {};
    float4 ra[2][2];
    float rb[2][8];

    const int NT = K3 / 16;  // 96
    ldg_km(Ag, K3, 0, tid, ra[0]);        ldg_conv(cbase, wbase, n0, 0, tid, rb[0]);
    ldg_km(Ag, K3, 16, tid, ra[1]);       ldg_conv(cbase, wbase, n0, 16, tid, rb[1]);
    sts_km(As[0], tid, ra[0]);            sts_conv(Bs[0], tid, rb[0]);
    __syncthreads();

    for (int kt = 0; kt < NT; kt++) {
        const int cur = kt & 1, nxt = cur ^ 1;
        if (kt + 2 < NT) {
            ldg_km(Ag, K3, (kt + 2) * 16, tid, ra[cur]);
            ldg_conv(cbase, wbase, n0, (kt + 2) * 16, tid, rb[cur]);
        }
        compute_tile(As[cur], Bs[cur], arow0, bcol0, gr, tg, acc);
        if (kt + 1 < NT) {
            sts_km(As[nxt], tid, ra[nxt]);
            sts_conv(Bs[nxt], tid, rb[nxt]);
            __syncthreads();
        }
    }

    float* dst = out + ((size_t)b * TGT) * TC;
#pragma unroll
    for (int mt = 0; mt < 4; mt++) {
        const int r0 = m0 + arow0 + mt * 16 + gr;   // o
        const float bs0 = bias[r0], bs1 = bias[r0 + 8];
#pragma unroll
        for (int nt = 0; nt < 4; nt++) {
            const int c = n0 + bcol0 + nt * 8 + tg * 2;  // t
            float2 v0 = { acc[mt][nt][0] + bs0, acc[mt][nt][1] + bs0 };
            float2 v1 = { acc[mt][nt][2] + bs1, acc[mt][nt][3] + bs1 };
            *(float2*)(dst + (size_t)r0 * TC + c) = v0;
            *(float2*)(dst + (size_t)(r0 + 8) * TC + c) = v1;
        }
    }
}

// ---------------------------------------------------------------------------
extern "C" void kernel_launch(void* const* d_in, const int* in_sizes, int n_in,
                              void* d_out, int out_size)
{
    const float* content = (const float*)d_in[0];  // [B][D][TC]
    const float* emotion = (const float*)d_in[1];  // [B][D][TE]
    const float* conv_w  = (const float*)d_in[2];  // [TGT][2D][3] = [TGT][1536]
    const float* conv_b  = (const float*)d_in[3];  // [TGT]
    float* out = (float*)d_out;                    // [B][TGT][TC]
    (void)in_sizes; (void)n_in; (void)out_size;

    gemm_qk<<<dim3(TC / 128, TE / 128, B), 256>>>(content, emotion);
    softmax_kernel<<<B * TC, 256>>>();
    gemm_av<<<dim3(TC / 128, D / 128, B), 256>>>(emotion);
    conv_mm<<<dim3(TC / 128, TGT / 128, B), 256>>>(content, conv_w, conv_b, out);
}